// round 7
// baseline (speedup 1.0000x reference)
#include <cuda_runtime.h>
#include <cuda_fp16.h>
#include <mma.h>
#include <cstdint>

using namespace nvcuda;

#define NN 8192
#define DD 64
#define GG 2048

// Scratch: fp32 dot/scores (256 MB), half P (128 MB), half X (32 MB),
// hi/lo-split encodings (3 MB each), norms.
__device__ float g_S[(size_t)NN * NN];
__device__ __half g_Ph[(size_t)NN * NN];
__device__ __half g_Xh[(size_t)NN * GG];
__device__ __half g_EA[(size_t)NN * 192];
__device__ __half g_EB[(size_t)NN * 192];
__device__ float g_norm[NN];

// ---------------------------------------------------------------------------
// helpers
// ---------------------------------------------------------------------------
__device__ __forceinline__ uint32_t smem_u32(const void* p) {
    uint32_t a;
    asm("{ .reg .u64 t; cvta.to.shared.u64 t, %1; cvt.u32.u64 %0, t; }" : "=r"(a) : "l"(p));
    return a;
}
__device__ __forceinline__ void cp_async16(uint32_t s, const void* g) {
    asm volatile("cp.async.cg.shared.global [%0], [%1], 16;" :: "r"(s), "l"(g));
}
__device__ __forceinline__ void cp_commit() {
    asm volatile("cp.async.commit_group;");
}
template <int N>
__device__ __forceinline__ void cp_wait() {
    asm volatile("cp.async.wait_group %0;" :: "n"(N));
}

// ---------------------------------------------------------------------------
// K1: row squared norms (fp32, exact)
// ---------------------------------------------------------------------------
__global__ void norms_kernel(const float* __restrict__ enc) {
    int i = blockIdx.x * blockDim.x + threadIdx.x;
    if (i >= NN) return;
    const float4* p = (const float4*)(enc + (size_t)i * DD);
    float s = 0.f;
#pragma unroll
    for (int k = 0; k < DD / 4; k++) {
        float4 v = p[k];
        s += v.x * v.x + v.y * v.y + v.z * v.z + v.w * v.w;
    }
    g_norm[i] = s;
}

// ---------------------------------------------------------------------------
// K1b: hi/lo split of encoding into K=192 concatenated operands:
//   EA = [hi | lo | hi], EB = [hi | hi | lo]  =>  EA·EB = hi·hi + lo·hi + hi·lo
// (drops only lo·lo ~1e-6 absolute; diagonal fixed exactly in softmax)
// ---------------------------------------------------------------------------
__global__ void split_enc_kernel(const float* __restrict__ enc) {
    int idx = blockIdx.x * blockDim.x + threadIdx.x;  // over NN*DD
    int row = idx >> 6;
    int col = idx & 63;
    float x = enc[idx];
    __half hi = __float2half_rn(x);
    __half lo = __float2half_rn(x - __half2float(hi));
    size_t b = (size_t)row * 192 + col;
    g_EA[b] = hi; g_EA[b + 64] = lo; g_EA[b + 128] = hi;
    g_EB[b] = hi; g_EB[b + 64] = hi; g_EB[b + 128] = lo;
}

// ---------------------------------------------------------------------------
// K2: dot[i,j] via fp16 wmma over K=192 (single smem load, 12 k-steps).
// 128x128 tile, 8 warps (2x4), warp 64x32. Writes raw dot to g_S.
// ---------------------------------------------------------------------------
#define SK 192
#define S_LDM 200
#define S_SMEM (2 * 128 * S_LDM * 2)  // 102400

__global__ void __launch_bounds__(256) scores_mm_kernel() {
    extern __shared__ __align__(16) char smem[];
    const uint32_t sbase = smem_u32(smem);
    __half* As = (__half*)smem;
    __half* Bs = (__half*)(smem + 128 * S_LDM * 2);
    const int tid = threadIdx.x;
    const int warp = tid >> 5;
    const int warp_m = warp >> 2;   // 0..1
    const int warp_n = warp & 3;    // 0..3
    const int i0 = blockIdx.y * 128;
    const int j0 = blockIdx.x * 128;

    const uint32_t sA = sbase;
    const uint32_t sB = sbase + 128 * S_LDM * 2;
#pragma unroll
    for (int h = 0; h < 12; h++) {
        int id = tid + h * 256;           // 0..3071
        int row = id / 24, c = id % 24;
        cp_async16(sA + row * (S_LDM * 2) + c * 16,
                   g_EA + (size_t)(i0 + row) * SK + c * 8);
        cp_async16(sB + row * (S_LDM * 2) + c * 16,
                   g_EB + (size_t)(j0 + row) * SK + c * 8);
    }
    cp_commit();
    cp_wait<0>();
    __syncthreads();

    wmma::fragment<wmma::accumulator, 16, 16, 16, float> cfr[4][2];
#pragma unroll
    for (int i = 0; i < 4; i++)
#pragma unroll
        for (int j = 0; j < 2; j++) wmma::fill_fragment(cfr[i][j], 0.f);

#pragma unroll
    for (int ks = 0; ks < SK; ks += 16) {
        wmma::fragment<wmma::matrix_a, 16, 16, 16, __half, wmma::row_major> a[4];
        wmma::fragment<wmma::matrix_b, 16, 16, 16, __half, wmma::col_major> b[2];
#pragma unroll
        for (int i = 0; i < 4; i++)
            wmma::load_matrix_sync(a[i], As + (warp_m * 64 + i * 16) * S_LDM + ks, S_LDM);
#pragma unroll
        for (int j = 0; j < 2; j++)
            wmma::load_matrix_sync(b[j], Bs + (warp_n * 32 + j * 16) * S_LDM + ks, S_LDM);
#pragma unroll
        for (int i = 0; i < 4; i++)
#pragma unroll
            for (int j = 0; j < 2; j++)
                wmma::mma_sync(cfr[i][j], a[i], b[j], cfr[i][j]);
    }

#pragma unroll
    for (int i = 0; i < 4; i++)
#pragma unroll
        for (int j = 0; j < 2; j++)
            wmma::store_matrix_sync(
                g_S + (size_t)(i0 + warp_m * 64 + i * 16) * NN + j0 + warp_n * 32 + j * 16,
                cfr[i][j], NN, wmma::mem_row_major);
}

// ---------------------------------------------------------------------------
// K3: fused score-transform + row softmax; fp32 dot in -> half P out.
// score = q[j] - sqrt(max(n_i + n_j - 2*dot, 0));  j==row -> exactly q[row]
// ---------------------------------------------------------------------------
__global__ void softmax_kernel(const float* __restrict__ qual) {
    const int row = blockIdx.x;
    const int tid = threadIdx.x;
    const float* S = g_S + (size_t)row * NN;
    __half* P = g_Ph + (size_t)row * NN;
    const float nrow = g_norm[row];

    float vals[32];
    float m = -1e30f;
#pragma unroll
    for (int k = 0; k < 32; k++) {
        int j = tid + k * 256;
        float d2 = nrow + g_norm[j] - 2.f * S[j];
        float sc = qual[j] - sqrtf(fmaxf(d2, 0.f));
        // True distance at the diagonal is exactly 0; the tensor dot drops the
        // lo*lo term which otherwise injects sqrt(~8e-6)=3e-3 of score error
        // at the softmax max.
        vals[k] = (j == row) ? qual[j] : sc;
        m = fmaxf(m, vals[k]);
    }

    __shared__ float red[8];
#pragma unroll
    for (int off = 16; off; off >>= 1) m = fmaxf(m, __shfl_xor_sync(~0u, m, off));
    if ((tid & 31) == 0) red[tid >> 5] = m;
    __syncthreads();
    if (tid < 8) {
        float x = red[tid];
#pragma unroll
        for (int off = 4; off; off >>= 1) x = fmaxf(x, __shfl_xor_sync(0xffu, x, off));
        if (tid == 0) red[0] = x;
    }
    __syncthreads();
    m = red[0];

    float s = 0.f;
#pragma unroll
    for (int k = 0; k < 32; k++) {
        vals[k] = __expf(vals[k] - m);
        s += vals[k];
    }
    __syncthreads();
#pragma unroll
    for (int off = 16; off; off >>= 1) s += __shfl_xor_sync(~0u, s, off);
    if ((tid & 31) == 0) red[tid >> 5] = s;
    __syncthreads();
    if (tid < 8) {
        float x = red[tid];
#pragma unroll
        for (int off = 4; off; off >>= 1) x += __shfl_xor_sync(0xffu, x, off);
        if (tid == 0) red[0] = x;
    }
    __syncthreads();
    float inv = 1.f / red[0];
#pragma unroll
    for (int k = 0; k < 32; k++) P[tid + k * 256] = __float2half_rn(vals[k] * inv);
}

// ---------------------------------------------------------------------------
// K3b: convert X (f32) -> half
// ---------------------------------------------------------------------------
__global__ void convx_kernel(const float* __restrict__ X) {
    size_t idx = ((size_t)blockIdx.x * blockDim.x + threadIdx.x) * 4;
    float4 v = *(const float4*)(X + idx);
    __half2* dst = (__half2*)(g_Xh + idx);
    dst[0] = __floats2half2_rn(v.x, v.y);
    dst[1] = __floats2half2_rn(v.z, v.w);
}

// ---------------------------------------------------------------------------
// K4: out = P @ X, fp16 wmma. Tile 128x256, BK=32, 4-stage cp.async.
// 8 warps (2x4), warp tile 64x64 (4x4 m16n16k16 frags).
// ---------------------------------------------------------------------------
#define BM 128
#define BN 256
#define BK 32
#define NSTG 4
#define A_LDM 40                          // halves
#define B_LDM 264                         // halves
#define A_STG_BYTES (BM * A_LDM * 2)      // 10240
#define B_STG_BYTES (BK * B_LDM * 2)      // 16896
#define STG_BYTES (A_STG_BYTES + B_STG_BYTES)
#define SMEM_GEMM (NSTG * STG_BYTES)      // 108544
#define NCHUNK (NN / BK)                  // 256

__device__ __forceinline__ void load_chunk(uint32_t sA, uint32_t sB,
                                           int m0, int n0, int c, int tid) {
    const size_t k0 = (size_t)c * BK;
    // A: 128 rows x 32 halves = 512 16B chunks
#pragma unroll
    for (int h = 0; h < 2; h++) {
        int ch = tid + h * 256;
        int row = ch >> 2, cc = ch & 3;
        cp_async16(sA + row * (A_LDM * 2) + cc * 16,
                   g_Ph + (size_t)(m0 + row) * NN + k0 + cc * 8);
    }
    // B: 32 rows x 256 halves = 1024 16B chunks
#pragma unroll
    for (int h = 0; h < 4; h++) {
        int ch = tid + h * 256;
        int row = ch >> 5, cc = ch & 31;
        cp_async16(sB + row * (B_LDM * 2) + cc * 16,
                   g_Xh + (size_t)(k0 + row) * GG + n0 + cc * 8);
    }
    cp_commit();
}

__global__ void __launch_bounds__(256) gemm_kernel(float* __restrict__ out) {
    extern __shared__ __align__(16) char smem[];
    const uint32_t sbase = smem_u32(smem);
    const int tid = threadIdx.x;
    const int warp = tid >> 5;
    const int warp_m = warp >> 2;   // 0..1
    const int warp_n = warp & 3;    // 0..3
    const int m0 = blockIdx.y * BM;
    const int n0 = blockIdx.x * BN;

    wmma::fragment<wmma::accumulator, 16, 16, 16, float> cfr[4][4];
#pragma unroll
    for (int i = 0; i < 4; i++)
#pragma unroll
        for (int j = 0; j < 4; j++) wmma::fill_fragment(cfr[i][j], 0.f);

#pragma unroll
    for (int c = 0; c < NSTG - 1; c++)
        load_chunk(sbase + c * STG_BYTES, sbase + c * STG_BYTES + A_STG_BYTES,
                   m0, n0, c, tid);

    for (int c = 0; c < NCHUNK; c++) {
        const int st = c % NSTG;
        const __half* Ah = (const __half*)(smem + st * STG_BYTES);
        const __half* Bh = (const __half*)(smem + st * STG_BYTES + A_STG_BYTES);

        if (c + 1 < NCHUNK) cp_wait<NSTG - 2>(); else cp_wait<0>();
        __syncthreads();

#pragma unroll
        for (int ks = 0; ks < BK; ks += 16) {
            wmma::fragment<wmma::matrix_a, 16, 16, 16, __half, wmma::row_major> a[4];
            wmma::fragment<wmma::matrix_b, 16, 16, 16, __half, wmma::row_major> b[4];
#pragma unroll
            for (int i = 0; i < 4; i++)
                wmma::load_matrix_sync(a[i], Ah + (warp_m * 64 + i * 16) * A_LDM + ks, A_LDM);
#pragma unroll
            for (int j = 0; j < 4; j++)
                wmma::load_matrix_sync(b[j], Bh + ks * B_LDM + warp_n * 64 + j * 16, B_LDM);
#pragma unroll
            for (int i = 0; i < 4; i++)
#pragma unroll
                for (int j = 0; j < 4; j++)
                    wmma::mma_sync(cfr[i][j], a[i], b[j], cfr[i][j]);
        }
        __syncthreads();

        if (c + NSTG - 1 < NCHUNK) {
            const int ns = (c + NSTG - 1) % NSTG;
            load_chunk(sbase + ns * STG_BYTES, sbase + ns * STG_BYTES + A_STG_BYTES,
                       m0, n0, c + NSTG - 1, tid);
        }
    }

#pragma unroll
    for (int i = 0; i < 4; i++)
#pragma unroll
        for (int j = 0; j < 4; j++)
            wmma::store_matrix_sync(
                out + (size_t)(m0 + warp_m * 64 + i * 16) * GG + n0 + warp_n * 64 + j * 16,
                cfr[i][j], GG, wmma::mem_row_major);
}

// ---------------------------------------------------------------------------
extern "C" void kernel_launch(void* const* d_in, const int* in_sizes, int n_in,
                              void* d_out, int out_size) {
    const float* expr = nullptr;  // N*G
    const float* enc = nullptr;   // N*D
    const float* qual = nullptr;  // N
    for (int i = 0; i < n_in; i++) {
        if (in_sizes[i] == NN * GG) expr = (const float*)d_in[i];
        else if (in_sizes[i] == NN * DD) enc = (const float*)d_in[i];
        else if (in_sizes[i] == NN) qual = (const float*)d_in[i];
    }
    float* out = (float*)d_out;

    cudaFuncSetAttribute(scores_mm_kernel, cudaFuncAttributeMaxDynamicSharedMemorySize,
                         S_SMEM);
    cudaFuncSetAttribute(gemm_kernel, cudaFuncAttributeMaxDynamicSharedMemorySize,
                         SMEM_GEMM);

    norms_kernel<<<NN / 256, 256>>>(enc);
    split_enc_kernel<<<(NN * DD) / 256, 256>>>(enc);
    dim3 g2(NN / 128, NN / 128);
    scores_mm_kernel<<<g2, 256, S_SMEM>>>();
    softmax_kernel<<<NN, 256>>>(qual);
    convx_kernel<<<(NN * GG) / (256 * 4), 256>>>(expr);
    dim3 g4(GG / BN, NN / BM);
    gemm_kernel<<<g4, 256, SMEM_GEMM>>>(out);
}

// round 8
// speedup vs baseline: 1.0334x; 1.0334x over previous
#include <cuda_runtime.h>
#include <cuda_fp16.h>
#include <mma.h>
#include <cstdint>

using namespace nvcuda;

#define NN 8192
#define DD 64
#define GG 2048

// Scratch: fp32 scores (256 MB), half P (128 MB), half X (32 MB),
// hi/lo-split encodings, norms.
__device__ float g_S[(size_t)NN * NN];
__device__ __half g_Ph[(size_t)NN * NN];
__device__ __half g_Xh[(size_t)NN * GG];
__device__ __half g_EA[(size_t)NN * 192];
__device__ __half g_EB[(size_t)NN * 192];
__device__ float g_norm[NN];

// ---------------------------------------------------------------------------
// helpers
// ---------------------------------------------------------------------------
__device__ __forceinline__ uint32_t smem_u32(const void* p) {
    uint32_t a;
    asm("{ .reg .u64 t; cvta.to.shared.u64 t, %1; cvt.u32.u64 %0, t; }" : "=r"(a) : "l"(p));
    return a;
}
__device__ __forceinline__ void cp_async16(uint32_t s, const void* g) {
    asm volatile("cp.async.cg.shared.global [%0], [%1], 16;" :: "r"(s), "l"(g));
}
__device__ __forceinline__ void cp_commit() {
    asm volatile("cp.async.commit_group;");
}
template <int N>
__device__ __forceinline__ void cp_wait() {
    asm volatile("cp.async.wait_group %0;" :: "n"(N));
}

// ---------------------------------------------------------------------------
// K1: row squared norms (fp32, exact)
// ---------------------------------------------------------------------------
__global__ void norms_kernel(const float* __restrict__ enc) {
    int i = blockIdx.x * blockDim.x + threadIdx.x;
    if (i >= NN) return;
    const float4* p = (const float4*)(enc + (size_t)i * DD);
    float s = 0.f;
#pragma unroll
    for (int k = 0; k < DD / 4; k++) {
        float4 v = p[k];
        s += v.x * v.x + v.y * v.y + v.z * v.z + v.w * v.w;
    }
    g_norm[i] = s;
}

// ---------------------------------------------------------------------------
// K1b: hi/lo split: EA=[hi|lo|hi], EB=[hi|hi|lo] => EA·EB = hh + lh + hl
// ---------------------------------------------------------------------------
__global__ void split_enc_kernel(const float* __restrict__ enc) {
    int idx = blockIdx.x * blockDim.x + threadIdx.x;  // over NN*DD
    int row = idx >> 6;
    int col = idx & 63;
    float x = enc[idx];
    __half hi = __float2half_rn(x);
    __half lo = __float2half_rn(x - __half2float(hi));
    size_t b = (size_t)row * 192 + col;
    g_EA[b] = hi; g_EA[b + 64] = lo; g_EA[b + 128] = hi;
    g_EB[b] = hi; g_EB[b + 64] = hi; g_EB[b + 128] = lo;
}

// ---------------------------------------------------------------------------
// K2: scores via fp16 wmma over K=192 + fused transform epilogue.
// Writes score = q[j] - sqrt(max(n_i + n_j - 2*dot, 0)) as fp32 to g_S.
// (sqrt MUFU work lives here, overlapping tensor work across blocks.)
// ---------------------------------------------------------------------------
#define SK 192
#define S_LDM 200
#define C_LDM 132
#define S_SMEM (2 * 128 * S_LDM * 2)  // 102400 (epilogue reuses it: 128*132*4=67584)

__global__ void __launch_bounds__(256) scores_mm_kernel(const float* __restrict__ qual) {
    extern __shared__ __align__(16) char smem[];
    const uint32_t sbase = smem_u32(smem);
    __half* As = (__half*)smem;
    __half* Bs = (__half*)(smem + 128 * S_LDM * 2);
    float* Cs = (float*)smem;
    const int tid = threadIdx.x;
    const int warp = tid >> 5;
    const int warp_m = warp >> 2;   // 0..1
    const int warp_n = warp & 3;    // 0..3
    const int i0 = blockIdx.y * 128;
    const int j0 = blockIdx.x * 128;

    const uint32_t sA = sbase;
    const uint32_t sB = sbase + 128 * S_LDM * 2;
#pragma unroll
    for (int h = 0; h < 12; h++) {
        int id = tid + h * 256;           // 0..3071
        int row = id / 24, c = id % 24;
        cp_async16(sA + row * (S_LDM * 2) + c * 16,
                   g_EA + (size_t)(i0 + row) * SK + c * 8);
        cp_async16(sB + row * (S_LDM * 2) + c * 16,
                   g_EB + (size_t)(j0 + row) * SK + c * 8);
    }
    cp_commit();
    cp_wait<0>();
    __syncthreads();

    wmma::fragment<wmma::accumulator, 16, 16, 16, float> cfr[4][2];
#pragma unroll
    for (int i = 0; i < 4; i++)
#pragma unroll
        for (int j = 0; j < 2; j++) wmma::fill_fragment(cfr[i][j], 0.f);

#pragma unroll
    for (int ks = 0; ks < SK; ks += 16) {
        wmma::fragment<wmma::matrix_a, 16, 16, 16, __half, wmma::row_major> a[4];
        wmma::fragment<wmma::matrix_b, 16, 16, 16, __half, wmma::col_major> b[2];
#pragma unroll
        for (int i = 0; i < 4; i++)
            wmma::load_matrix_sync(a[i], As + (warp_m * 64 + i * 16) * S_LDM + ks, S_LDM);
#pragma unroll
        for (int j = 0; j < 2; j++)
            wmma::load_matrix_sync(b[j], Bs + (warp_n * 32 + j * 16) * S_LDM + ks, S_LDM);
#pragma unroll
        for (int i = 0; i < 4; i++)
#pragma unroll
            for (int j = 0; j < 2; j++)
                wmma::mma_sync(cfr[i][j], a[i], b[j], cfr[i][j]);
    }

    // Epilogue: frags -> smem -> transform -> fp32 scores to g_S
    __syncthreads();  // done reading As/Bs
#pragma unroll
    for (int i = 0; i < 4; i++)
#pragma unroll
        for (int j = 0; j < 2; j++)
            wmma::store_matrix_sync(
                Cs + (warp_m * 64 + i * 16) * C_LDM + warp_n * 32 + j * 16,
                cfr[i][j], C_LDM, wmma::mem_row_major);
    __syncthreads();

    {
        const int r = tid >> 1;             // 0..127
        const int ch = (tid & 1) * 64;      // 0 or 64
        const int i = i0 + r;
        const float nrow = g_norm[i];
        float* orow = g_S + (size_t)i * NN + j0 + ch;
        const float* crow = Cs + r * C_LDM + ch;
#pragma unroll
        for (int c4 = 0; c4 < 64; c4 += 4) {
            float4 d = *(const float4*)(crow + c4);
            int j = j0 + ch + c4;
            float4 o;
            o.x = qual[j + 0] - sqrtf(fmaxf(nrow + g_norm[j + 0] - 2.f * d.x, 0.f));
            o.y = qual[j + 1] - sqrtf(fmaxf(nrow + g_norm[j + 1] - 2.f * d.y, 0.f));
            o.z = qual[j + 2] - sqrtf(fmaxf(nrow + g_norm[j + 2] - 2.f * d.z, 0.f));
            o.w = qual[j + 3] - sqrtf(fmaxf(nrow + g_norm[j + 3] - 2.f * d.w, 0.f));
            *(float4*)(orow + c4) = o;
        }
    }
}

// ---------------------------------------------------------------------------
// K3: row softmax (round-4 shape: exp only). Diagonal score forced to
// qual[row] (true distance 0; tensor dot drops lo*lo there).
// ---------------------------------------------------------------------------
__global__ void softmax_kernel(const float* __restrict__ qual) {
    const int row = blockIdx.x;
    const int tid = threadIdx.x;
    const float* S = g_S + (size_t)row * NN;
    __half* P = g_Ph + (size_t)row * NN;

    float vals[32];
    float m = -1e30f;
#pragma unroll
    for (int k = 0; k < 32; k++) {
        int j = tid + k * 256;
        float sc = S[j];
        vals[k] = (j == row) ? qual[row] : sc;
        m = fmaxf(m, vals[k]);
    }

    __shared__ float red[8];
#pragma unroll
    for (int off = 16; off; off >>= 1) m = fmaxf(m, __shfl_xor_sync(~0u, m, off));
    if ((tid & 31) == 0) red[tid >> 5] = m;
    __syncthreads();
    if (tid < 8) {
        float x = red[tid];
#pragma unroll
        for (int off = 4; off; off >>= 1) x = fmaxf(x, __shfl_xor_sync(0xffu, x, off));
        if (tid == 0) red[0] = x;
    }
    __syncthreads();
    m = red[0];

    float s = 0.f;
#pragma unroll
    for (int k = 0; k < 32; k++) {
        vals[k] = __expf(vals[k] - m);
        s += vals[k];
    }
    __syncthreads();
#pragma unroll
    for (int off = 16; off; off >>= 1) s += __shfl_xor_sync(~0u, s, off);
    if ((tid & 31) == 0) red[tid >> 5] = s;
    __syncthreads();
    if (tid < 8) {
        float x = red[tid];
#pragma unroll
        for (int off = 4; off; off >>= 1) x += __shfl_xor_sync(0xffu, x, off);
        if (tid == 0) red[0] = x;
    }
    __syncthreads();
    float inv = 1.f / red[0];
#pragma unroll
    for (int k = 0; k < 32; k++) P[tid + k * 256] = __float2half_rn(vals[k] * inv);
}

// ---------------------------------------------------------------------------
// K3b: convert X (f32) -> half
// ---------------------------------------------------------------------------
__global__ void convx_kernel(const float* __restrict__ X) {
    size_t idx = ((size_t)blockIdx.x * blockDim.x + threadIdx.x) * 4;
    float4 v = *(const float4*)(X + idx);
    __half2* dst = (__half2*)(g_Xh + idx);
    dst[0] = __floats2half2_rn(v.x, v.y);
    dst[1] = __floats2half2_rn(v.z, v.w);
}

// ---------------------------------------------------------------------------
// K4: out = P @ X, fp16 wmma. Tile 128x256, BK=32, 3-stage cp.async,
// 512 threads = 16 warps (2x8), warp tile 64x32 (round-4 reg pressure).
// ---------------------------------------------------------------------------
#define BM 128
#define BN 256
#define BK 32
#define NSTG 3
#define A_LDM 40                          // halves
#define B_LDM 264                         // halves
#define A_STG_BYTES (BM * A_LDM * 2)      // 10240
#define B_STG_BYTES (BK * B_LDM * 2)      // 16896
#define STG_BYTES (A_STG_BYTES + B_STG_BYTES)
#define SMEM_GEMM (NSTG * STG_BYTES)      // 81408
#define NCHUNK (NN / BK)                  // 256

__device__ __forceinline__ void load_chunk(uint32_t sA, uint32_t sB,
                                           int m0, int n0, int c, int tid) {
    const size_t k0 = (size_t)c * BK;
    // A: 128 rows x 32 halves = 512 16B chunks (1 per thread)
    {
        int row = tid >> 2, cc = tid & 3;
        cp_async16(sA + row * (A_LDM * 2) + cc * 16,
                   g_Ph + (size_t)(m0 + row) * NN + k0 + cc * 8);
    }
    // B: 32 rows x 256 halves = 1024 16B chunks (2 per thread)
#pragma unroll
    for (int h = 0; h < 2; h++) {
        int ch = tid + h * 512;
        int row = ch >> 5, cc = ch & 31;
        cp_async16(sB + row * (B_LDM * 2) + cc * 16,
                   g_Xh + (size_t)(k0 + row) * GG + n0 + cc * 8);
    }
    cp_commit();
}

__global__ void __launch_bounds__(512) gemm_kernel(float* __restrict__ out) {
    extern __shared__ __align__(16) char smem[];
    const uint32_t sbase = smem_u32(smem);
    const int tid = threadIdx.x;
    const int warp = tid >> 5;
    const int warp_m = warp >> 3;   // 0..1
    const int warp_n = warp & 7;    // 0..7
    const int m0 = blockIdx.y * BM;
    const int n0 = blockIdx.x * BN;

    wmma::fragment<wmma::accumulator, 16, 16, 16, float> cfr[4][2];
#pragma unroll
    for (int i = 0; i < 4; i++)
#pragma unroll
        for (int j = 0; j < 2; j++) wmma::fill_fragment(cfr[i][j], 0.f);

#pragma unroll
    for (int c = 0; c < NSTG - 1; c++)
        load_chunk(sbase + c * STG_BYTES, sbase + c * STG_BYTES + A_STG_BYTES,
                   m0, n0, c, tid);

    for (int c = 0; c < NCHUNK; c++) {
        const int st = c % NSTG;
        const __half* Ah = (const __half*)(smem + st * STG_BYTES);
        const __half* Bh = (const __half*)(smem + st * STG_BYTES + A_STG_BYTES);

        if (c + 1 < NCHUNK) cp_wait<NSTG - 2>(); else cp_wait<0>();
        __syncthreads();

#pragma unroll
        for (int ks = 0; ks < BK; ks += 16) {
            wmma::fragment<wmma::matrix_a, 16, 16, 16, __half, wmma::row_major> a[4];
            wmma::fragment<wmma::matrix_b, 16, 16, 16, __half, wmma::row_major> b[2];
#pragma unroll
            for (int i = 0; i < 4; i++)
                wmma::load_matrix_sync(a[i], Ah + (warp_m * 64 + i * 16) * A_LDM + ks, A_LDM);
#pragma unroll
            for (int j = 0; j < 2; j++)
                wmma::load_matrix_sync(b[j], Bh + ks * B_LDM + warp_n * 32 + j * 16, B_LDM);
#pragma unroll
            for (int i = 0; i < 4; i++)
#pragma unroll
                for (int j = 0; j < 2; j++)
                    wmma::mma_sync(cfr[i][j], a[i], b[j], cfr[i][j]);
        }
        __syncthreads();

        if (c + NSTG - 1 < NCHUNK) {
            const int ns = (c + NSTG - 1) % NSTG;
            load_chunk(sbase + ns * STG_BYTES, sbase + ns * STG_BYTES + A_STG_BYTES,
                       m0, n0, c + NSTG - 1, tid);
        }
    }

#pragma unroll
    for (int i = 0; i < 4; i++)
#pragma unroll
        for (int j = 0; j < 2; j++)
            wmma::store_matrix_sync(
                out + (size_t)(m0 + warp_m * 64 + i * 16) * GG + n0 + warp_n * 32 + j * 16,
                cfr[i][j], GG, wmma::mem_row_major);
}

// ---------------------------------------------------------------------------
extern "C" void kernel_launch(void* const* d_in, const int* in_sizes, int n_in,
                              void* d_out, int out_size) {
    const float* expr = nullptr;  // N*G
    const float* enc = nullptr;   // N*D
    const float* qual = nullptr;  // N
    for (int i = 0; i < n_in; i++) {
        if (in_sizes[i] == NN * GG) expr = (const float*)d_in[i];
        else if (in_sizes[i] == NN * DD) enc = (const float*)d_in[i];
        else if (in_sizes[i] == NN) qual = (const float*)d_in[i];
    }
    float* out = (float*)d_out;

    cudaFuncSetAttribute(scores_mm_kernel, cudaFuncAttributeMaxDynamicSharedMemorySize,
                         S_SMEM);
    cudaFuncSetAttribute(gemm_kernel, cudaFuncAttributeMaxDynamicSharedMemorySize,
                         SMEM_GEMM);

    norms_kernel<<<NN / 256, 256>>>(enc);
    split_enc_kernel<<<(NN * DD) / 256, 256>>>(enc);
    dim3 g2(NN / 128, NN / 128);
    scores_mm_kernel<<<g2, 256, S_SMEM>>>(qual);
    softmax_kernel<<<NN, 256>>>(qual);
    convx_kernel<<<(NN * GG) / (256 * 4), 256>>>(expr);
    dim3 g4(GG / BN, NN / BM);
    gemm_kernel<<<g4, 512, SMEM_GEMM>>>(out);
}

// round 11
// speedup vs baseline: 1.2465x; 1.2062x over previous
#include <cuda_runtime.h>
#include <cuda_fp16.h>
#include <mma.h>
#include <cstdint>

using namespace nvcuda;

#define NN 8192
#define DD 64
#define GG 2048

// Scratch: fp32 scores (256 MB), half P (128 MB), half X (32 MB),
// hi/lo-split encodings, norms.
__device__ float g_S[(size_t)NN * NN];
__device__ __half g_Ph[(size_t)NN * NN];
__device__ __half g_Xh[(size_t)NN * GG];
__device__ __half g_EA[(size_t)NN * 192];
__device__ __half g_EB[(size_t)NN * 192];
__device__ float g_norm[NN];

// ---------------------------------------------------------------------------
// helpers
// ---------------------------------------------------------------------------
__device__ __forceinline__ uint32_t smem_u32(const void* p) {
    uint32_t a;
    asm("{ .reg .u64 t; cvta.to.shared.u64 t, %1; cvt.u32.u64 %0, t; }" : "=r"(a) : "l"(p));
    return a;
}
__device__ __forceinline__ void cp_async16(uint32_t s, const void* g) {
    asm volatile("cp.async.cg.shared.global [%0], [%1], 16;" :: "r"(s), "l"(g));
}
__device__ __forceinline__ void cp_commit() {
    asm volatile("cp.async.commit_group;");
}
template <int N>
__device__ __forceinline__ void cp_wait() {
    asm volatile("cp.async.wait_group %0;" :: "n"(N));
}

// ---------------------------------------------------------------------------
// K1: row squared norms (fp32, exact)
// ---------------------------------------------------------------------------
__global__ void norms_kernel(const float* __restrict__ enc) {
    int i = blockIdx.x * blockDim.x + threadIdx.x;
    if (i >= NN) return;
    const float4* p = (const float4*)(enc + (size_t)i * DD);
    float s = 0.f;
#pragma unroll
    for (int k = 0; k < DD / 4; k++) {
        float4 v = p[k];
        s += v.x * v.x + v.y * v.y + v.z * v.z + v.w * v.w;
    }
    g_norm[i] = s;
}

// ---------------------------------------------------------------------------
// K1b: hi/lo split: EA=[hi|lo|hi], EB=[hi|hi|lo] => EA·EB = hh + lh + hl
// ---------------------------------------------------------------------------
__global__ void split_enc_kernel(const float* __restrict__ enc) {
    int idx = blockIdx.x * blockDim.x + threadIdx.x;  // over NN*DD
    int row = idx >> 6;
    int col = idx & 63;
    float x = enc[idx];
    __half hi = __float2half_rn(x);
    __half lo = __float2half_rn(x - __half2float(hi));
    size_t b = (size_t)row * 192 + col;
    g_EA[b] = hi; g_EA[b + 64] = lo; g_EA[b + 128] = hi;
    g_EB[b] = hi; g_EB[b + 64] = hi; g_EB[b + 128] = lo;
}

// ---------------------------------------------------------------------------
// K2: scores via fp16 wmma over K=192 in 3 pipelined chunks of 64,
// fused transform epilogue: g_S = q[j] - sqrt(max(n_i+n_j-2*dot, 0)).
// 2 CTAs/SM (reg-capped), 3 cp.async groups with incremental waits.
// ---------------------------------------------------------------------------
#define SK_CH 64
#define S_LDM 72                             // halves, padded
#define S_TILE (128 * S_LDM * 2)             // 18432 B
#define S_CHUNK (2 * S_TILE)                 // A+B per chunk = 36864
#define C_LDM 132
#define S_SMEM (3 * S_CHUNK)                 // 110592 (>= 128*132*4 epilogue)

__global__ void __launch_bounds__(256, 2) scores_mm_kernel(const float* __restrict__ qual) {
    extern __shared__ __align__(16) char smem[];
    const uint32_t sbase = smem_u32(smem);
    float* Cs = (float*)smem;
    const int tid = threadIdx.x;
    const int warp = tid >> 5;
    const int warp_m = warp >> 2;   // 0..1
    const int warp_n = warp & 3;    // 0..3
    const int i0 = blockIdx.y * 128;
    const int j0 = blockIdx.x * 128;

    // Issue all 3 chunk loads as separate commit groups.
#pragma unroll
    for (int s = 0; s < 3; s++) {
        const uint32_t sA = sbase + s * S_CHUNK;
        const uint32_t sB = sA + S_TILE;
        const int koff = s * SK_CH;
#pragma unroll
        for (int h = 0; h < 4; h++) {
            int id = tid + h * 256;          // 0..1023
            int row = id >> 3, cc = id & 7;  // 8 x 16B per row
            cp_async16(sA + row * (S_LDM * 2) + cc * 16,
                       g_EA + (size_t)(i0 + row) * 192 + koff + cc * 8);
            cp_async16(sB + row * (S_LDM * 2) + cc * 16,
                       g_EB + (size_t)(j0 + row) * 192 + koff + cc * 8);
        }
        cp_commit();
    }

    wmma::fragment<wmma::accumulator, 16, 16, 16, float> cfr[4][2];
#pragma unroll
    for (int i = 0; i < 4; i++)
#pragma unroll
        for (int j = 0; j < 2; j++) wmma::fill_fragment(cfr[i][j], 0.f);

#pragma unroll
    for (int s = 0; s < 3; s++) {
        if (s == 0) cp_wait<2>();
        else if (s == 1) cp_wait<1>();
        else cp_wait<0>();
        __syncthreads();
        const __half* As = (const __half*)(smem + s * S_CHUNK);
        const __half* Bs = (const __half*)(smem + s * S_CHUNK + S_TILE);
#pragma unroll
        for (int ks = 0; ks < SK_CH; ks += 16) {
            wmma::fragment<wmma::matrix_a, 16, 16, 16, __half, wmma::row_major> a[4];
            wmma::fragment<wmma::matrix_b, 16, 16, 16, __half, wmma::col_major> b[2];
#pragma unroll
            for (int i = 0; i < 4; i++)
                wmma::load_matrix_sync(a[i], As + (warp_m * 64 + i * 16) * S_LDM + ks, S_LDM);
#pragma unroll
            for (int j = 0; j < 2; j++)
                wmma::load_matrix_sync(b[j], Bs + (warp_n * 32 + j * 16) * S_LDM + ks, S_LDM);
#pragma unroll
            for (int i = 0; i < 4; i++)
#pragma unroll
                for (int j = 0; j < 2; j++)
                    wmma::mma_sync(cfr[i][j], a[i], b[j], cfr[i][j]);
        }
    }

    // Epilogue: frags -> smem -> transform -> fp32 scores to g_S
    __syncthreads();
#pragma unroll
    for (int i = 0; i < 4; i++)
#pragma unroll
        for (int j = 0; j < 2; j++)
            wmma::store_matrix_sync(
                Cs + (warp_m * 64 + i * 16) * C_LDM + warp_n * 32 + j * 16,
                cfr[i][j], C_LDM, wmma::mem_row_major);
    __syncthreads();

    {
        const int r = tid >> 1;             // 0..127
        const int ch = (tid & 1) * 64;      // 0 or 64
        const int i = i0 + r;
        const float nrow = g_norm[i];
        float* orow = g_S + (size_t)i * NN + j0 + ch;
        const float* crow = Cs + r * C_LDM + ch;
#pragma unroll
        for (int c4 = 0; c4 < 64; c4 += 4) {
            float4 d = *(const float4*)(crow + c4);
            int j = j0 + ch + c4;
            float4 o;
            o.x = qual[j + 0] - sqrtf(fmaxf(nrow + g_norm[j + 0] - 2.f * d.x, 0.f));
            o.y = qual[j + 1] - sqrtf(fmaxf(nrow + g_norm[j + 1] - 2.f * d.y, 0.f));
            o.z = qual[j + 2] - sqrtf(fmaxf(nrow + g_norm[j + 2] - 2.f * d.z, 0.f));
            o.w = qual[j + 3] - sqrtf(fmaxf(nrow + g_norm[j + 3] - 2.f * d.w, 0.f));
            *(float4*)(orow + c4) = o;
        }
    }
}

// ---------------------------------------------------------------------------
// K3: row softmax (exp only). Diagonal forced to qual[row] (true distance 0).
// ---------------------------------------------------------------------------
__global__ void softmax_kernel(const float* __restrict__ qual) {
    const int row = blockIdx.x;
    const int tid = threadIdx.x;
    const float* S = g_S + (size_t)row * NN;
    __half* P = g_Ph + (size_t)row * NN;

    float vals[32];
    float m = -1e30f;
#pragma unroll
    for (int k = 0; k < 32; k++) {
        int j = tid + k * 256;
        float sc = S[j];
        vals[k] = (j == row) ? qual[row] : sc;
        m = fmaxf(m, vals[k]);
    }

    __shared__ float red[8];
#pragma unroll
    for (int off = 16; off; off >>= 1) m = fmaxf(m, __shfl_xor_sync(~0u, m, off));
    if ((tid & 31) == 0) red[tid >> 5] = m;
    __syncthreads();
    if (tid < 8) {
        float x = red[tid];
#pragma unroll
        for (int off = 4; off; off >>= 1) x = fmaxf(x, __shfl_xor_sync(0xffu, x, off));
        if (tid == 0) red[0] = x;
    }
    __syncthreads();
    m = red[0];

    float s = 0.f;
#pragma unroll
    for (int k = 0; k < 32; k++) {
        vals[k] = __expf(vals[k] - m);
        s += vals[k];
    }
    __syncthreads();
#pragma unroll
    for (int off = 16; off; off >>= 1) s += __shfl_xor_sync(~0u, s, off);
    if ((tid & 31) == 0) red[tid >> 5] = s;
    __syncthreads();
    if (tid < 8) {
        float x = red[tid];
#pragma unroll
        for (int off = 4; off; off >>= 1) x += __shfl_xor_sync(0xffu, x, off);
        if (tid == 0) red[0] = x;
    }
    __syncthreads();
    float inv = 1.f / red[0];
#pragma unroll
    for (int k = 0; k < 32; k++) P[tid + k * 256] = __float2half_rn(vals[k] * inv);
}

// ---------------------------------------------------------------------------
// K3b: convert X (f32) -> half
// ---------------------------------------------------------------------------
__global__ void convx_kernel(const float* __restrict__ X) {
    size_t idx = ((size_t)blockIdx.x * blockDim.x + threadIdx.x) * 4;
    float4 v = *(const float4*)(X + idx);
    __half2* dst = (__half2*)(g_Xh + idx);
    dst[0] = __floats2half2_rn(v.x, v.y);
    dst[1] = __floats2half2_rn(v.z, v.w);
}

// ---------------------------------------------------------------------------
// K4: out = P @ X, fp16 wmma. Tile 128x128, BK=64, 3-stage cp.async,
// 256 threads = 8 warps (2x4), warp tile 64x32, 2 CTAs/SM (reg-capped).
// Grid is N-major so concurrent blocks share A rows through L2.
// ---------------------------------------------------------------------------
#define BM 128
#define BN 128
#define BK 64
#define NSTG 3
#define A_LDM 72                          // halves (64 data + 8 pad)
#define B_LDM 136                         // halves (128 data + 8 pad)
#define A_STG_BYTES (BM * A_LDM * 2)      // 18432
#define B_STG_BYTES (BK * B_LDM * 2)      // 17408
#define STG_BYTES (A_STG_BYTES + B_STG_BYTES)
#define SMEM_GEMM (NSTG * STG_BYTES)      // 107520
#define NCHUNK (NN / BK)                  // 128

__device__ __forceinline__ void load_chunk(uint32_t sA, uint32_t sB,
                                           int m0, int n0, int c, int tid) {
    const size_t k0 = (size_t)c * BK;
    // A: 128 rows x 64 halves (128B/row) = 1024 16B chunks, 4/thread
#pragma unroll
    for (int h = 0; h < 4; h++) {
        int id = tid + h * 256;
        int row = id >> 3, cc = id & 7;
        cp_async16(sA + row * (A_LDM * 2) + cc * 16,
                   g_Ph + (size_t)(m0 + row) * NN + k0 + cc * 8);
    }
    // B: 64 rows x 128 halves (256B/row) = 1024 16B chunks, 4/thread
#pragma unroll
    for (int h = 0; h < 4; h++) {
        int id = tid + h * 256;
        int row = id >> 4, cc = id & 15;
        cp_async16(sB + row * (B_LDM * 2) + cc * 16,
                   g_Xh + (size_t)(k0 + row) * GG + n0 + cc * 8);
    }
    cp_commit();
}

__global__ void __launch_bounds__(256, 2) gemm_kernel(float* __restrict__ out) {
    extern __shared__ __align__(16) char smem[];
    const uint32_t sbase = smem_u32(smem);
    const int tid = threadIdx.x;
    const int warp = tid >> 5;
    const int warp_m = warp >> 2;   // 0..1
    const int warp_n = warp & 3;    // 0..3
    const int m0 = blockIdx.y * BM;
    const int n0 = blockIdx.x * BN;

    wmma::fragment<wmma::accumulator, 16, 16, 16, float> cfr[4][2];
#pragma unroll
    for (int i = 0; i < 4; i++)
#pragma unroll
        for (int j = 0; j < 2; j++) wmma::fill_fragment(cfr[i][j], 0.f);

#pragma unroll
    for (int c = 0; c < NSTG - 1; c++)
        load_chunk(sbase + c * STG_BYTES, sbase + c * STG_BYTES + A_STG_BYTES,
                   m0, n0, c, tid);

    for (int c = 0; c < NCHUNK; c++) {
        const int st = c % NSTG;
        const __half* Ah = (const __half*)(smem + st * STG_BYTES);
        const __half* Bh = (const __half*)(smem + st * STG_BYTES + A_STG_BYTES);

        if (c + 1 < NCHUNK) cp_wait<NSTG - 2>(); else cp_wait<0>();
        __syncthreads();

#pragma unroll
        for (int ks = 0; ks < BK; ks += 16) {
            wmma::fragment<wmma::matrix_a, 16, 16, 16, __half, wmma::row_major> a[4];
            wmma::fragment<wmma::matrix_b, 16, 16, 16, __half, wmma::row_major> b[2];
#pragma unroll
            for (int i = 0; i < 4; i++)
                wmma::load_matrix_sync(a[i], Ah + (warp_m * 64 + i * 16) * A_LDM + ks, A_LDM);
#pragma unroll
            for (int j = 0; j < 2; j++)
                wmma::load_matrix_sync(b[j], Bh + ks * B_LDM + warp_n * 32 + j * 16, B_LDM);
#pragma unroll
            for (int i = 0; i < 4; i++)
#pragma unroll
                for (int j = 0; j < 2; j++)
                    wmma::mma_sync(cfr[i][j], a[i], b[j], cfr[i][j]);
        }
        __syncthreads();

        if (c + NSTG - 1 < NCHUNK) {
            const int ns = (c + NSTG - 1) % NSTG;
            load_chunk(sbase + ns * STG_BYTES, sbase + ns * STG_BYTES + A_STG_BYTES,
                       m0, n0, c + NSTG - 1, tid);
        }
    }

#pragma unroll
    for (int i = 0; i < 4; i++)
#pragma unroll
        for (int j = 0; j < 2; j++)
            wmma::store_matrix_sync(
                out + (size_t)(m0 + warp_m * 64 + i * 16) * GG + n0 + warp_n * 32 + j * 16,
                cfr[i][j], GG, wmma::mem_row_major);
}

// ---------------------------------------------------------------------------
extern "C" void kernel_launch(void* const* d_in, const int* in_sizes, int n_in,
                              void* d_out, int out_size) {
    const float* expr = nullptr;  // N*G
    const float* enc = nullptr;   // N*D
    const float* qual = nullptr;  // N
    for (int i = 0; i < n_in; i++) {
        if (in_sizes[i] == NN * GG) expr = (const float*)d_in[i];
        else if (in_sizes[i] == NN * DD) enc = (const float*)d_in[i];
        else if (in_sizes[i] == NN) qual = (const float*)d_in[i];
    }
    float* out = (float*)d_out;

    cudaFuncSetAttribute(scores_mm_kernel, cudaFuncAttributeMaxDynamicSharedMemorySize,
                         S_SMEM);
    cudaFuncSetAttribute(gemm_kernel, cudaFuncAttributeMaxDynamicSharedMemorySize,
                         SMEM_GEMM);

    norms_kernel<<<NN / 256, 256>>>(enc);
    split_enc_kernel<<<(NN * DD) / 256, 256>>>(enc);
    dim3 g2(NN / 128, NN / 128);
    scores_mm_kernel<<<g2, 256, S_SMEM>>>(qual);
    softmax_kernel<<<NN, 256>>>(qual);
    convx_kernel<<<(NN * GG) / (256 * 4), 256>>>(expr);
    dim3 g4(GG / BN, NN / BM);
    gemm_kernel<<<g4, 256, SMEM_GEMM>>>(out);
}

// round 12
// speedup vs baseline: 1.3438x; 1.0781x over previous
#include <cuda_runtime.h>
#include <cuda_fp16.h>
#include <mma.h>
#include <cstdint>

using namespace nvcuda;

#define NN 8192
#define DD 64
#define GG 2048

// Scratch: fp32 scores (256 MB), half P (128 MB), half X (32 MB),
// hi/lo-split encodings (K=128), norms.
__device__ float g_S[(size_t)NN * NN];
__device__ __half g_Ph[(size_t)NN * NN];
__device__ __half g_Xh[(size_t)NN * GG];
__device__ __half g_EA[(size_t)NN * 128];
__device__ __half g_EB[(size_t)NN * 128];
__device__ float g_norm[NN];

// ---------------------------------------------------------------------------
// helpers
// ---------------------------------------------------------------------------
__device__ __forceinline__ uint32_t smem_u32(const void* p) {
    uint32_t a;
    asm("{ .reg .u64 t; cvta.to.shared.u64 t, %1; cvt.u32.u64 %0, t; }" : "=r"(a) : "l"(p));
    return a;
}
__device__ __forceinline__ void cp_async16(uint32_t s, const void* g) {
    asm volatile("cp.async.cg.shared.global [%0], [%1], 16;" :: "r"(s), "l"(g));
}
__device__ __forceinline__ void cp_commit() {
    asm volatile("cp.async.commit_group;");
}
template <int N>
__device__ __forceinline__ void cp_wait() {
    asm volatile("cp.async.wait_group %0;" :: "n"(N));
}

// ---------------------------------------------------------------------------
// K1: row squared norms (fp32, exact)
// ---------------------------------------------------------------------------
__global__ void norms_kernel(const float* __restrict__ enc) {
    int i = blockIdx.x * blockDim.x + threadIdx.x;
    if (i >= NN) return;
    const float4* p = (const float4*)(enc + (size_t)i * DD);
    float s = 0.f;
#pragma unroll
    for (int k = 0; k < DD / 4; k++) {
        float4 v = p[k];
        s += v.x * v.x + v.y * v.y + v.z * v.z + v.w * v.w;
    }
    g_norm[i] = s;
}

// ---------------------------------------------------------------------------
// K1b: asymmetric hi/lo split (K=128):
//   EA = [hi | lo], EB = [hi | hi]  =>  EA·EB = hh + lh
// (drops hl + ll: ~1e-4 score error; diagonal fixed exactly in softmax)
// ---------------------------------------------------------------------------
__global__ void split_enc_kernel(const float* __restrict__ enc) {
    int idx = blockIdx.x * blockDim.x + threadIdx.x;  // over NN*DD
    int row = idx >> 6;
    int col = idx & 63;
    float x = enc[idx];
    __half hi = __float2half_rn(x);
    __half lo = __float2half_rn(x - __half2float(hi));
    size_t b = (size_t)row * 128 + col;
    g_EA[b] = hi; g_EA[b + 64] = lo;
    g_EB[b] = hi; g_EB[b + 64] = hi;
}

// ---------------------------------------------------------------------------
// K2: scores via fp16 wmma over K=128 in 2 pipelined chunks of 64,
// fused transform epilogue: g_S = q[j] - sqrt(max(n_i+n_j-2*dot, 0)).
// 2 CTAs/SM (reg-capped).
// ---------------------------------------------------------------------------
#define SK_CH 64
#define S_LDM 72                             // halves, padded
#define S_TILE (128 * S_LDM * 2)             // 18432 B
#define S_CHUNK (2 * S_TILE)                 // A+B per chunk = 36864
#define C_LDM 132
#define S_SMEM (2 * S_CHUNK)                 // 73728 (>= 128*132*4 epilogue)

__global__ void __launch_bounds__(256, 2) scores_mm_kernel(const float* __restrict__ qual) {
    extern __shared__ __align__(16) char smem[];
    const uint32_t sbase = smem_u32(smem);
    float* Cs = (float*)smem;
    const int tid = threadIdx.x;
    const int warp = tid >> 5;
    const int warp_m = warp >> 2;   // 0..1
    const int warp_n = warp & 3;    // 0..3
    const int i0 = blockIdx.y * 128;
    const int j0 = blockIdx.x * 128;

    // Issue both chunk loads as separate commit groups.
#pragma unroll
    for (int s = 0; s < 2; s++) {
        const uint32_t sA = sbase + s * S_CHUNK;
        const uint32_t sB = sA + S_TILE;
        const int koff = s * SK_CH;
#pragma unroll
        for (int h = 0; h < 4; h++) {
            int id = tid + h * 256;          // 0..1023
            int row = id >> 3, cc = id & 7;  // 8 x 16B per row
            cp_async16(sA + row * (S_LDM * 2) + cc * 16,
                       g_EA + (size_t)(i0 + row) * 128 + koff + cc * 8);
            cp_async16(sB + row * (S_LDM * 2) + cc * 16,
                       g_EB + (size_t)(j0 + row) * 128 + koff + cc * 8);
        }
        cp_commit();
    }

    wmma::fragment<wmma::accumulator, 16, 16, 16, float> cfr[4][2];
#pragma unroll
    for (int i = 0; i < 4; i++)
#pragma unroll
        for (int j = 0; j < 2; j++) wmma::fill_fragment(cfr[i][j], 0.f);

#pragma unroll
    for (int s = 0; s < 2; s++) {
        if (s == 0) cp_wait<1>();
        else cp_wait<0>();
        __syncthreads();
        const __half* As = (const __half*)(smem + s * S_CHUNK);
        const __half* Bs = (const __half*)(smem + s * S_CHUNK + S_TILE);
#pragma unroll
        for (int ks = 0; ks < SK_CH; ks += 16) {
            wmma::fragment<wmma::matrix_a, 16, 16, 16, __half, wmma::row_major> a[4];
            wmma::fragment<wmma::matrix_b, 16, 16, 16, __half, wmma::col_major> b[2];
#pragma unroll
            for (int i = 0; i < 4; i++)
                wmma::load_matrix_sync(a[i], As + (warp_m * 64 + i * 16) * S_LDM + ks, S_LDM);
#pragma unroll
            for (int j = 0; j < 2; j++)
                wmma::load_matrix_sync(b[j], Bs + (warp_n * 32 + j * 16) * S_LDM + ks, S_LDM);
#pragma unroll
            for (int i = 0; i < 4; i++)
#pragma unroll
                for (int j = 0; j < 2; j++)
                    wmma::mma_sync(cfr[i][j], a[i], b[j], cfr[i][j]);
        }
    }

    // Epilogue: frags -> smem -> transform -> fp32 scores to g_S
    __syncthreads();
#pragma unroll
    for (int i = 0; i < 4; i++)
#pragma unroll
        for (int j = 0; j < 2; j++)
            wmma::store_matrix_sync(
                Cs + (warp_m * 64 + i * 16) * C_LDM + warp_n * 32 + j * 16,
                cfr[i][j], C_LDM, wmma::mem_row_major);
    __syncthreads();

    {
        const int r = tid >> 1;             // 0..127
        const int ch = (tid & 1) * 64;      // 0 or 64
        const int i = i0 + r;
        const float nrow = g_norm[i];
        float* orow = g_S + (size_t)i * NN + j0 + ch;
        const float* crow = Cs + r * C_LDM + ch;
#pragma unroll
        for (int c4 = 0; c4 < 64; c4 += 4) {
            float4 d = *(const float4*)(crow + c4);
            int j = j0 + ch + c4;
            float4 o;
            o.x = qual[j + 0] - sqrtf(fmaxf(nrow + g_norm[j + 0] - 2.f * d.x, 0.f));
            o.y = qual[j + 1] - sqrtf(fmaxf(nrow + g_norm[j + 1] - 2.f * d.y, 0.f));
            o.z = qual[j + 2] - sqrtf(fmaxf(nrow + g_norm[j + 2] - 2.f * d.z, 0.f));
            o.w = qual[j + 3] - sqrtf(fmaxf(nrow + g_norm[j + 3] - 2.f * d.w, 0.f));
            *(float4*)(orow + c4) = o;
        }
    }
}

// ---------------------------------------------------------------------------
// K3: row softmax (exp only). Diagonal forced to qual[row] (true distance 0).
// ---------------------------------------------------------------------------
__global__ void softmax_kernel(const float* __restrict__ qual) {
    const int row = blockIdx.x;
    const int tid = threadIdx.x;
    const float* S = g_S + (size_t)row * NN;
    __half* P = g_Ph + (size_t)row * NN;

    float vals[32];
    float m = -1e30f;
#pragma unroll
    for (int k = 0; k < 32; k++) {
        int j = tid + k * 256;
        float sc = S[j];
        vals[k] = (j == row) ? qual[row] : sc;
        m = fmaxf(m, vals[k]);
    }

    __shared__ float red[8];
#pragma unroll
    for (int off = 16; off; off >>= 1) m = fmaxf(m, __shfl_xor_sync(~0u, m, off));
    if ((tid & 31) == 0) red[tid >> 5] = m;
    __syncthreads();
    if (tid < 8) {
        float x = red[tid];
#pragma unroll
        for (int off = 4; off; off >>= 1) x = fmaxf(x, __shfl_xor_sync(0xffu, x, off));
        if (tid == 0) red[0] = x;
    }
    __syncthreads();
    m = red[0];

    float s = 0.f;
#pragma unroll
    for (int k = 0; k < 32; k++) {
        vals[k] = __expf(vals[k] - m);
        s += vals[k];
    }
    __syncthreads();
#pragma unroll
    for (int off = 16; off; off >>= 1) s += __shfl_xor_sync(~0u, s, off);
    if ((tid & 31) == 0) red[tid >> 5] = s;
    __syncthreads();
    if (tid < 8) {
        float x = red[tid];
#pragma unroll
        for (int off = 4; off; off >>= 1) x += __shfl_xor_sync(0xffu, x, off);
        if (tid == 0) red[0] = x;
    }
    __syncthreads();
    float inv = 1.f / red[0];
#pragma unroll
    for (int k = 0; k < 32; k++) P[tid + k * 256] = __float2half_rn(vals[k] * inv);
}

// ---------------------------------------------------------------------------
// K3b: convert X (f32) -> half
// ---------------------------------------------------------------------------
__global__ void convx_kernel(const float* __restrict__ X) {
    size_t idx = ((size_t)blockIdx.x * blockDim.x + threadIdx.x) * 4;
    float4 v = *(const float4*)(X + idx);
    __half2* dst = (__half2*)(g_Xh + idx);
    dst[0] = __floats2half2_rn(v.x, v.y);
    dst[1] = __floats2half2_rn(v.z, v.w);
}

// ---------------------------------------------------------------------------
// K4: out = P @ X, fp16 wmma. Tile 128x128, BK=64, 3-stage cp.async,
// single-sync multistage mainloop (load issue overlaps MMA), 2 CTAs/SM.
// ---------------------------------------------------------------------------
#define BM 128
#define BN 128
#define BK 64
#define NSTG 3
#define A_LDM 72                          // halves (64 data + 8 pad)
#define B_LDM 136                         // halves (128 data + 8 pad)
#define A_STG_BYTES (BM * A_LDM * 2)      // 18432
#define B_STG_BYTES (BK * B_LDM * 2)      // 17408
#define STG_BYTES (A_STG_BYTES + B_STG_BYTES)
#define SMEM_GEMM (NSTG * STG_BYTES)      // 107520
#define NCHUNK (NN / BK)                  // 128

__device__ __forceinline__ void load_chunk(uint32_t sA, uint32_t sB,
                                           int m0, int n0, int c, int tid) {
    const size_t k0 = (size_t)c * BK;
    // A: 128 rows x 64 halves (128B/row) = 1024 16B chunks, 4/thread
#pragma unroll
    for (int h = 0; h < 4; h++) {
        int id = tid + h * 256;
        int row = id >> 3, cc = id & 7;
        cp_async16(sA + row * (A_LDM * 2) + cc * 16,
                   g_Ph + (size_t)(m0 + row) * NN + k0 + cc * 8);
    }
    // B: 64 rows x 128 halves (256B/row) = 1024 16B chunks, 4/thread
#pragma unroll
    for (int h = 0; h < 4; h++) {
        int id = tid + h * 256;
        int row = id >> 4, cc = id & 15;
        cp_async16(sB + row * (B_LDM * 2) + cc * 16,
                   g_Xh + (size_t)(k0 + row) * GG + n0 + cc * 16 / 2);
    }
    cp_commit();
}

__global__ void __launch_bounds__(256, 2) gemm_kernel(float* __restrict__ out) {
    extern __shared__ __align__(16) char smem[];
    const uint32_t sbase = smem_u32(smem);
    const int tid = threadIdx.x;
    const int warp = tid >> 5;
    const int warp_m = warp >> 2;   // 0..1
    const int warp_n = warp & 3;    // 0..3
    const int m0 = blockIdx.y * BM;
    const int n0 = blockIdx.x * BN;

    wmma::fragment<wmma::accumulator, 16, 16, 16, float> cfr[4][2];
#pragma unroll
    for (int i = 0; i < 4; i++)
#pragma unroll
        for (int j = 0; j < 2; j++) wmma::fill_fragment(cfr[i][j], 0.f);

#pragma unroll
    for (int c = 0; c < NSTG - 1; c++)
        load_chunk(sbase + c * STG_BYTES, sbase + c * STG_BYTES + A_STG_BYTES,
                   m0, n0, c, tid);

    for (int c = 0; c < NCHUNK; c++) {
        const int st = c % NSTG;
        const __half* Ah = (const __half*)(smem + st * STG_BYTES);
        const __half* Bh = (const __half*)(smem + st * STG_BYTES + A_STG_BYTES);

        if (c + 1 < NCHUNK) cp_wait<NSTG - 2>(); else cp_wait<0>();
        __syncthreads();
        // Issue the next load into the stage freed by last iteration's compute
        // (the sync above proves all warps are done with it). Overlaps MMA.
        if (c + NSTG - 1 < NCHUNK) {
            const int ns = (c + NSTG - 1) % NSTG;
            load_chunk(sbase + ns * STG_BYTES, sbase + ns * STG_BYTES + A_STG_BYTES,
                       m0, n0, c + NSTG - 1, tid);
        }

#pragma unroll
        for (int ks = 0; ks < BK; ks += 16) {
            wmma::fragment<wmma::matrix_a, 16, 16, 16, __half, wmma::row_major> a[4];
            wmma::fragment<wmma::matrix_b, 16, 16, 16, __half, wmma::row_major> b[2];
#pragma unroll
            for (int i = 0; i < 4; i++)
                wmma::load_matrix_sync(a[i], Ah + (warp_m * 64 + i * 16) * A_LDM + ks, A_LDM);
#pragma unroll
            for (int j = 0; j < 2; j++)
                wmma::load_matrix_sync(b[j], Bh + ks * B_LDM + warp_n * 32 + j * 16, B_LDM);
#pragma unroll
            for (int i = 0; i < 4; i++)
#pragma unroll
                for (int j = 0; j < 2; j++)
                    wmma::mma_sync(cfr[i][j], a[i], b[j], cfr[i][j]);
        }
    }

#pragma unroll
    for (int i = 0; i < 4; i++)
#pragma unroll
        for (int j = 0; j < 2; j++)
            wmma::store_matrix_sync(
                out + (size_t)(m0 + warp_m * 64 + i * 16) * GG + n0 + warp_n * 32 + j * 16,
                cfr[i][j], GG, wmma::mem_row_major);
}

// ---------------------------------------------------------------------------
extern "C" void kernel_launch(void* const* d_in, const int* in_sizes, int n_in,
                              void* d_out, int out_size) {
    const float* expr = nullptr;  // N*G
    const float* enc = nullptr;   // N*D
    const float* qual = nullptr;  // N
    for (int i = 0; i < n_in; i++) {
        if (in_sizes[i] == NN * GG) expr = (const float*)d_in[i];
        else if (in_sizes[i] == NN * DD) enc = (const float*)d_in[i];
        else if (in_sizes[i] == NN) qual = (const float*)d_in[i];
    }
    float* out = (float*)d_out;

    cudaFuncSetAttribute(scores_mm_kernel, cudaFuncAttributeMaxDynamicSharedMemorySize,
                         S_SMEM);
    cudaFuncSetAttribute(gemm_kernel, cudaFuncAttributeMaxDynamicSharedMemorySize,
                         SMEM_GEMM);

    norms_kernel<<<NN / 256, 256>>>(enc);
    split_enc_kernel<<<(NN * DD) / 256, 256>>>(enc);
    dim3 g2(NN / 128, NN / 128);
    scores_mm_kernel<<<g2, 256, S_SMEM>>>(qual);
    softmax_kernel<<<NN, 256>>>(qual);
    convx_kernel<<<(NN * GG) / (256 * 4), 256>>>(expr);
    dim3 g4(GG / BN, NN / BM);
    gemm_kernel<<<g4, 256, SMEM_GEMM>>>(out);
}

// round 13
// speedup vs baseline: 1.4130x; 1.0515x over previous
#include <cuda_runtime.h>
#include <cuda_fp16.h>
#include <mma.h>
#include <cstdint>

using namespace nvcuda;

#define NN 8192
#define DD 64
#define GG 2048

// Scratch: fp32 scores (256 MB), half P (128 MB), half X (32 MB),
// hi/lo-split encodings (K=128), norms.
__device__ float g_S[(size_t)NN * NN];
__device__ __half g_Ph[(size_t)NN * NN];
__device__ __half g_Xh[(size_t)NN * GG];
__device__ __half g_EA[(size_t)NN * 128];
__device__ __half g_EB[(size_t)NN * 128];
__device__ float g_norm[NN];

// ---------------------------------------------------------------------------
// helpers
// ---------------------------------------------------------------------------
__device__ __forceinline__ uint32_t smem_u32(const void* p) {
    uint32_t a;
    asm("{ .reg .u64 t; cvta.to.shared.u64 t, %1; cvt.u32.u64 %0, t; }" : "=r"(a) : "l"(p));
    return a;
}
__device__ __forceinline__ void cp_async16(uint32_t s, const void* g) {
    asm volatile("cp.async.cg.shared.global [%0], [%1], 16;" :: "r"(s), "l"(g));
}
__device__ __forceinline__ void cp_commit() {
    asm volatile("cp.async.commit_group;");
}
template <int N>
__device__ __forceinline__ void cp_wait() {
    asm volatile("cp.async.wait_group %0;" :: "n"(N));
}

// ---------------------------------------------------------------------------
// K1: row squared norms (fp32, exact)
// ---------------------------------------------------------------------------
__global__ void norms_kernel(const float* __restrict__ enc) {
    int i = blockIdx.x * blockDim.x + threadIdx.x;
    if (i >= NN) return;
    const float4* p = (const float4*)(enc + (size_t)i * DD);
    float s = 0.f;
#pragma unroll
    for (int k = 0; k < DD / 4; k++) {
        float4 v = p[k];
        s += v.x * v.x + v.y * v.y + v.z * v.z + v.w * v.w;
    }
    g_norm[i] = s;
}

// ---------------------------------------------------------------------------
// K1b: asymmetric hi/lo split (K=128):
//   EA = [hi | lo], EB = [hi | hi]  =>  EA·EB = hh + lh
// (drops hl + ll: ~1e-4 score error; diagonal fixed exactly in softmax)
// ---------------------------------------------------------------------------
__global__ void split_enc_kernel(const float* __restrict__ enc) {
    int idx = blockIdx.x * blockDim.x + threadIdx.x;  // over NN*DD
    int row = idx >> 6;
    int col = idx & 63;
    float x = enc[idx];
    __half hi = __float2half_rn(x);
    __half lo = __float2half_rn(x - __half2float(hi));
    size_t b = (size_t)row * 128 + col;
    g_EA[b] = hi; g_EA[b + 64] = lo;
    g_EB[b] = hi; g_EB[b + 64] = hi;
}

// ---------------------------------------------------------------------------
// K2: scores via fp16 wmma over K=128 in 2 pipelined chunks of 64,
// fused transform epilogue: g_S = q[j] - sqrt(max(n_i+n_j-2*dot, 0)).
// 2 CTAs/SM (reg-capped).
// ---------------------------------------------------------------------------
#define SK_CH 64
#define S_LDM 72                             // halves, padded
#define S_TILE (128 * S_LDM * 2)             // 18432 B
#define S_CHUNK (2 * S_TILE)                 // A+B per chunk = 36864
#define C_LDM 132
#define S_SMEM (2 * S_CHUNK)                 // 73728 (>= 128*132*4 epilogue)

__global__ void __launch_bounds__(256, 2) scores_mm_kernel(const float* __restrict__ qual) {
    extern __shared__ __align__(16) char smem[];
    const uint32_t sbase = smem_u32(smem);
    float* Cs = (float*)smem;
    const int tid = threadIdx.x;
    const int warp = tid >> 5;
    const int warp_m = warp >> 2;   // 0..1
    const int warp_n = warp & 3;    // 0..3
    const int i0 = blockIdx.y * 128;
    const int j0 = blockIdx.x * 128;

    // Issue both chunk loads as separate commit groups (pointer-carried).
    {
        const int row = tid >> 3, cc = tid & 7;
        const __half* pA = g_EA + (size_t)(i0 + row) * 128 + cc * 8;
        const __half* pB = g_EB + (size_t)(j0 + row) * 128 + cc * 8;
        const uint32_t dA = sbase + row * (S_LDM * 2) + cc * 16;
        const uint32_t dB = dA + S_TILE;
#pragma unroll
        for (int s = 0; s < 2; s++) {
            const uint32_t so = s * S_CHUNK;
            const int ko = s * SK_CH;
            cp_async16(dA + so,                  pA + ko);
            cp_async16(dA + so + 32 * S_LDM * 2, pA + ko + (size_t)32 * 128);
            cp_async16(dA + so + 64 * S_LDM * 2, pA + ko + (size_t)64 * 128);
            cp_async16(dA + so + 96 * S_LDM * 2, pA + ko + (size_t)96 * 128);
            cp_async16(dB + so,                  pB + ko);
            cp_async16(dB + so + 32 * S_LDM * 2, pB + ko + (size_t)32 * 128);
            cp_async16(dB + so + 64 * S_LDM * 2, pB + ko + (size_t)64 * 128);
            cp_async16(dB + so + 96 * S_LDM * 2, pB + ko + (size_t)96 * 128);
            cp_commit();
        }
    }

    wmma::fragment<wmma::accumulator, 16, 16, 16, float> cfr[4][2];
#pragma unroll
    for (int i = 0; i < 4; i++)
#pragma unroll
        for (int j = 0; j < 2; j++) wmma::fill_fragment(cfr[i][j], 0.f);

#pragma unroll
    for (int s = 0; s < 2; s++) {
        if (s == 0) cp_wait<1>();
        else cp_wait<0>();
        __syncthreads();
        const __half* As = (const __half*)(smem + s * S_CHUNK);
        const __half* Bs = (const __half*)(smem + s * S_CHUNK + S_TILE);
#pragma unroll
        for (int ks = 0; ks < SK_CH; ks += 16) {
            wmma::fragment<wmma::matrix_a, 16, 16, 16, __half, wmma::row_major> a[4];
            wmma::fragment<wmma::matrix_b, 16, 16, 16, __half, wmma::col_major> b[2];
#pragma unroll
            for (int i = 0; i < 4; i++)
                wmma::load_matrix_sync(a[i], As + (warp_m * 64 + i * 16) * S_LDM + ks, S_LDM);
#pragma unroll
            for (int j = 0; j < 2; j++)
                wmma::load_matrix_sync(b[j], Bs + (warp_n * 32 + j * 16) * S_LDM + ks, S_LDM);
#pragma unroll
            for (int i = 0; i < 4; i++)
#pragma unroll
                for (int j = 0; j < 2; j++)
                    wmma::mma_sync(cfr[i][j], a[i], b[j], cfr[i][j]);
        }
    }

    // Epilogue: frags -> smem -> transform -> fp32 scores to g_S
    __syncthreads();
#pragma unroll
    for (int i = 0; i < 4; i++)
#pragma unroll
        for (int j = 0; j < 2; j++)
            wmma::store_matrix_sync(
                Cs + (warp_m * 64 + i * 16) * C_LDM + warp_n * 32 + j * 16,
                cfr[i][j], C_LDM, wmma::mem_row_major);
    __syncthreads();

    {
        const int r = tid >> 1;             // 0..127
        const int ch = (tid & 1) * 64;      // 0 or 64
        const int i = i0 + r;
        const float nrow = g_norm[i];
        float* orow = g_S + (size_t)i * NN + j0 + ch;
        const float* crow = Cs + r * C_LDM + ch;
#pragma unroll
        for (int c4 = 0; c4 < 64; c4 += 4) {
            float4 d = *(const float4*)(crow + c4);
            int j = j0 + ch + c4;
            float4 o;
            o.x = qual[j + 0] - sqrtf(fmaxf(nrow + g_norm[j + 0] - 2.f * d.x, 0.f));
            o.y = qual[j + 1] - sqrtf(fmaxf(nrow + g_norm[j + 1] - 2.f * d.y, 0.f));
            o.z = qual[j + 2] - sqrtf(fmaxf(nrow + g_norm[j + 2] - 2.f * d.z, 0.f));
            o.w = qual[j + 3] - sqrtf(fmaxf(nrow + g_norm[j + 3] - 2.f * d.w, 0.f));
            *(float4*)(orow + c4) = o;
        }
    }
}

// ---------------------------------------------------------------------------
// K3: row softmax (exp only). Diagonal forced to qual[row] (true distance 0).
// ---------------------------------------------------------------------------
__global__ void softmax_kernel(const float* __restrict__ qual) {
    const int row = blockIdx.x;
    const int tid = threadIdx.x;
    const float* S = g_S + (size_t)row * NN;
    __half* P = g_Ph + (size_t)row * NN;

    float vals[32];
    float m = -1e30f;
#pragma unroll
    for (int k = 0; k < 32; k++) {
        int j = tid + k * 256;
        float sc = S[j];
        vals[k] = (j == row) ? qual[row] : sc;
        m = fmaxf(m, vals[k]);
    }

    __shared__ float red[8];
#pragma unroll
    for (int off = 16; off; off >>= 1) m = fmaxf(m, __shfl_xor_sync(~0u, m, off));
    if ((tid & 31) == 0) red[tid >> 5] = m;
    __syncthreads();
    if (tid < 8) {
        float x = red[tid];
#pragma unroll
        for (int off = 4; off; off >>= 1) x = fmaxf(x, __shfl_xor_sync(0xffu, x, off));
        if (tid == 0) red[0] = x;
    }
    __syncthreads();
    m = red[0];

    float s = 0.f;
#pragma unroll
    for (int k = 0; k < 32; k++) {
        vals[k] = __expf(vals[k] - m);
        s += vals[k];
    }
    __syncthreads();
#pragma unroll
    for (int off = 16; off; off >>= 1) s += __shfl_xor_sync(~0u, s, off);
    if ((tid & 31) == 0) red[tid >> 5] = s;
    __syncthreads();
    if (tid < 8) {
        float x = red[tid];
#pragma unroll
        for (int off = 4; off; off >>= 1) x += __shfl_xor_sync(0xffu, x, off);
        if (tid == 0) red[0] = x;
    }
    __syncthreads();
    float inv = 1.f / red[0];
#pragma unroll
    for (int k = 0; k < 32; k++) P[tid + k * 256] = __float2half_rn(vals[k] * inv);
}

// ---------------------------------------------------------------------------
// K3b: convert X (f32) -> half
// ---------------------------------------------------------------------------
__global__ void convx_kernel(const float* __restrict__ X) {
    size_t idx = ((size_t)blockIdx.x * blockDim.x + threadIdx.x) * 4;
    float4 v = *(const float4*)(X + idx);
    __half2* dst = (__half2*)(g_Xh + idx);
    dst[0] = __floats2half2_rn(v.x, v.y);
    dst[1] = __floats2half2_rn(v.z, v.w);
}

// ---------------------------------------------------------------------------
// K4: out = P @ X, fp16 wmma. Tile 128x128, BK=64, 3-stage cp.async,
// single-sync multistage mainloop, 2 CTAs/SM. Load addressing is
// pointer-carried: per-thread bases + constant offsets (folds to [R+imm]),
// ~2 integer ops per chunk instead of ~50 (issue-port relief).
// ---------------------------------------------------------------------------
#define BM 128
#define BN 128
#define BK 64
#define NSTG 3
#define A_LDM 72                          // halves (64 data + 8 pad)
#define B_LDM 136                         // halves (128 data + 8 pad)
#define A_STG_BYTES (BM * A_LDM * 2)      // 18432
#define B_STG_BYTES (BK * B_LDM * 2)      // 17408
#define STG_BYTES (A_STG_BYTES + B_STG_BYTES)
#define SMEM_GEMM (NSTG * STG_BYTES)      // 107520
#define NCHUNK (NN / BK)                  // 128

__global__ void __launch_bounds__(256, 2) gemm_kernel(float* __restrict__ out) {
    extern __shared__ __align__(16) char smem[];
    const uint32_t sbase = smem_u32(smem);
    const int tid = threadIdx.x;
    const int warp = tid >> 5;
    const int warp_m = warp >> 2;   // 0..1
    const int warp_n = warp & 3;    // 0..3
    const int m0 = blockIdx.y * BM;
    const int n0 = blockIdx.x * BN;

    // Pointer-carried load state (per thread, invariant shapes).
    const int aRow = tid >> 3, aCol = tid & 7;     // A: 128r x 8 chunks of 16B
    const int bRow = tid >> 4, bCol = tid & 15;    // B: 64r(÷4) x 16 chunks of 16B
    const __half* pA = g_Ph + (size_t)(m0 + aRow) * NN + aCol * 8;
    const __half* pB = g_Xh + (size_t)bRow * GG + n0 + bCol * 8;
    const uint32_t dA0 = sbase + aRow * (A_LDM * 2) + aCol * 16;
    const uint32_t dB0 = sbase + A_STG_BYTES + bRow * (B_LDM * 2) + bCol * 16;

#define ISSUE_CHUNK(stg) do {                                                  \
        const uint32_t _o = (uint32_t)(stg) * STG_BYTES;                       \
        cp_async16(dA0 + _o,                   pA);                            \
        cp_async16(dA0 + _o + 32 * A_LDM * 2,  pA + (size_t)32 * NN);          \
        cp_async16(dA0 + _o + 64 * A_LDM * 2,  pA + (size_t)64 * NN);          \
        cp_async16(dA0 + _o + 96 * A_LDM * 2,  pA + (size_t)96 * NN);          \
        cp_async16(dB0 + _o,                   pB);                            \
        cp_async16(dB0 + _o + 16 * B_LDM * 2,  pB + (size_t)16 * GG);          \
        cp_async16(dB0 + _o + 32 * B_LDM * 2,  pB + (size_t)32 * GG);          \
        cp_async16(dB0 + _o + 48 * B_LDM * 2,  pB + (size_t)48 * GG);          \
        cp_commit();                                                           \
        pA += BK;                                                              \
        pB += (size_t)BK * GG;                                                 \
    } while (0)

    wmma::fragment<wmma::accumulator, 16, 16, 16, float> cfr[4][2];
#pragma unroll
    for (int i = 0; i < 4; i++)
#pragma unroll
        for (int j = 0; j < 2; j++) wmma::fill_fragment(cfr[i][j], 0.f);

    ISSUE_CHUNK(0);
    ISSUE_CHUNK(1);

    for (int c = 0; c < NCHUNK; c++) {
        const int st = c % NSTG;
        const __half* Ah = (const __half*)(smem + st * STG_BYTES);
        const __half* Bh = (const __half*)(smem + st * STG_BYTES + A_STG_BYTES);

        if (c + 1 < NCHUNK) cp_wait<NSTG - 2>(); else cp_wait<0>();
        __syncthreads();
        // Refill the stage freed by the previous iteration (sync above proves
        // every warp is done with it). LDGSTS issue overlaps the MMAs below.
        if (c + NSTG - 1 < NCHUNK) ISSUE_CHUNK((c + NSTG - 1) % NSTG);

#pragma unroll
        for (int ks = 0; ks < BK; ks += 16) {
            wmma::fragment<wmma::matrix_a, 16, 16, 16, __half, wmma::row_major> a[4];
            wmma::fragment<wmma::matrix_b, 16, 16, 16, __half, wmma::row_major> b[2];
#pragma unroll
            for (int i = 0; i < 4; i++)
                wmma::load_matrix_sync(a[i], Ah + (warp_m * 64 + i * 16) * A_LDM + ks, A_LDM);
#pragma unroll
            for (int j = 0; j < 2; j++)
                wmma::load_matrix_sync(b[j], Bh + ks * B_LDM + warp_n * 32 + j * 16, B_LDM);
#pragma unroll
            for (int i = 0; i < 4; i++)
#pragma unroll
                for (int j = 0; j < 2; j++)
                    wmma::mma_sync(cfr[i][j], a[i], b[j], cfr[i][j]);
        }
    }
#undef ISSUE_CHUNK

#pragma unroll
    for (int i = 0; i < 4; i++)
#pragma unroll
        for (int j = 0; j < 2; j++)
            wmma::store_matrix_sync(
                out + (size_t)(m0 + warp_m * 64 + i * 16) * GG + n0 + warp_n * 32 + j * 16,
                cfr[i][j], GG, wmma::mem_row_major);
}

// ---------------------------------------------------------------------------
extern "C" void kernel_launch(void* const* d_in, const int* in_sizes, int n_in,
                              void* d_out, int out_size) {
    const float* expr = nullptr;  // N*G
    const float* enc = nullptr;   // N*D
    const float* qual = nullptr;  // N
    for (int i = 0; i < n_in; i++) {
        if (in_sizes[i] == NN * GG) expr = (const float*)d_in[i];
        else if (in_sizes[i] == NN * DD) enc = (const float*)d_in[i];
        else if (in_sizes[i] == NN) qual = (const float*)d_in[i];
    }
    float* out = (float*)d_out;

    cudaFuncSetAttribute(scores_mm_kernel, cudaFuncAttributeMaxDynamicSharedMemorySize,
                         S_SMEM);
    cudaFuncSetAttribute(gemm_kernel, cudaFuncAttributeMaxDynamicSharedMemorySize,
                         SMEM_GEMM);

    norms_kernel<<<NN / 256, 256>>>(enc);
    split_enc_kernel<<<(NN * DD) / 256, 256>>>(enc);
    dim3 g2(NN / 128, NN / 128);
    scores_mm_kernel<<<g2, 256, S_SMEM>>>(qual);
    softmax_kernel<<<NN, 256>>>(qual);
    convx_kernel<<<(NN * GG) / (256 * 4), 256>>>(expr);
    dim3 g4(GG / BN, NN / BM);
    gemm_kernel<<<g4, 256, SMEM_GEMM>>>(out);
}

// round 14
// speedup vs baseline: 1.4421x; 1.0206x over previous
#include <cuda_runtime.h>
#include <cuda_fp16.h>
#include <mma.h>
#include <cstdint>

using namespace nvcuda;

#define NN 8192
#define DD 64
#define GG 2048

// Scratch: fp32 scores (256 MB), half P (128 MB), half X (32 MB),
// hi/lo-split encodings (K=128), norms.
__device__ float g_S[(size_t)NN * NN];
__device__ __half g_Ph[(size_t)NN * NN];
__device__ __half g_Xh[(size_t)NN * GG];
__device__ __half g_EA[(size_t)NN * 128];
__device__ __half g_EB[(size_t)NN * 128];
__device__ float g_norm[NN];

// ---------------------------------------------------------------------------
// helpers
// ---------------------------------------------------------------------------
__device__ __forceinline__ uint32_t smem_u32(const void* p) {
    uint32_t a;
    asm("{ .reg .u64 t; cvta.to.shared.u64 t, %1; cvt.u32.u64 %0, t; }" : "=r"(a) : "l"(p));
    return a;
}
__device__ __forceinline__ void cp_async16(uint32_t s, const void* g) {
    asm volatile("cp.async.cg.shared.global [%0], [%1], 16;" :: "r"(s), "l"(g));
}
__device__ __forceinline__ void cp_commit() {
    asm volatile("cp.async.commit_group;");
}
template <int N>
__device__ __forceinline__ void cp_wait() {
    asm volatile("cp.async.wait_group %0;" :: "n"(N));
}

// ---------------------------------------------------------------------------
// K1: row squared norms (fp32, exact)
// ---------------------------------------------------------------------------
__global__ void norms_kernel(const float* __restrict__ enc) {
    int i = blockIdx.x * blockDim.x + threadIdx.x;
    if (i >= NN) return;
    const float4* p = (const float4*)(enc + (size_t)i * DD);
    float s = 0.f;
#pragma unroll
    for (int k = 0; k < DD / 4; k++) {
        float4 v = p[k];
        s += v.x * v.x + v.y * v.y + v.z * v.z + v.w * v.w;
    }
    g_norm[i] = s;
}

// ---------------------------------------------------------------------------
// K1b: asymmetric hi/lo split (K=128):
//   EA = [hi | lo], EB = [hi | hi]  =>  EA·EB = hh + lh
// (drops hl + ll: ~1e-4 score error; diagonal fixed exactly in softmax)
// ---------------------------------------------------------------------------
__global__ void split_enc_kernel(const float* __restrict__ enc) {
    int idx = blockIdx.x * blockDim.x + threadIdx.x;  // over NN*DD
    int row = idx >> 6;
    int col = idx & 63;
    float x = enc[idx];
    __half hi = __float2half_rn(x);
    __half lo = __float2half_rn(x - __half2float(hi));
    size_t b = (size_t)row * 128 + col;
    g_EA[b] = hi; g_EA[b + 64] = lo;
    g_EB[b] = hi; g_EB[b + 64] = hi;
}

// ---------------------------------------------------------------------------
// K2: scores via fp16 wmma over K=128 in 2 pipelined chunks of 64,
// fused transform epilogue: g_S = q[j] - sqrt(max(n_i+n_j-2*dot, 0)).
// 2 CTAs/SM (reg-capped). Epilogue norm/qual gathers are float4.
// ---------------------------------------------------------------------------
#define SK_CH 64
#define S_LDM 72                             // halves, padded
#define S_TILE (128 * S_LDM * 2)             // 18432 B
#define S_CHUNK (2 * S_TILE)                 // A+B per chunk = 36864
#define C_LDM 132
#define S_SMEM (2 * S_CHUNK)                 // 73728 (>= 128*132*4 epilogue)

__global__ void __launch_bounds__(256, 2) scores_mm_kernel(const float* __restrict__ qual) {
    extern __shared__ __align__(16) char smem[];
    const uint32_t sbase = smem_u32(smem);
    float* Cs = (float*)smem;
    const int tid = threadIdx.x;
    const int warp = tid >> 5;
    const int warp_m = warp >> 2;   // 0..1
    const int warp_n = warp & 3;    // 0..3
    const int i0 = blockIdx.y * 128;
    const int j0 = blockIdx.x * 128;

    // Issue both chunk loads as separate commit groups (pointer-carried).
    {
        const int row = tid >> 3, cc = tid & 7;
        const __half* pA = g_EA + (size_t)(i0 + row) * 128 + cc * 8;
        const __half* pB = g_EB + (size_t)(j0 + row) * 128 + cc * 8;
        const uint32_t dA = sbase + row * (S_LDM * 2) + cc * 16;
        const uint32_t dB = dA + S_TILE;
#pragma unroll
        for (int s = 0; s < 2; s++) {
            const uint32_t so = s * S_CHUNK;
            const int ko = s * SK_CH;
            cp_async16(dA + so,                  pA + ko);
            cp_async16(dA + so + 32 * S_LDM * 2, pA + ko + (size_t)32 * 128);
            cp_async16(dA + so + 64 * S_LDM * 2, pA + ko + (size_t)64 * 128);
            cp_async16(dA + so + 96 * S_LDM * 2, pA + ko + (size_t)96 * 128);
            cp_async16(dB + so,                  pB + ko);
            cp_async16(dB + so + 32 * S_LDM * 2, pB + ko + (size_t)32 * 128);
            cp_async16(dB + so + 64 * S_LDM * 2, pB + ko + (size_t)64 * 128);
            cp_async16(dB + so + 96 * S_LDM * 2, pB + ko + (size_t)96 * 128);
            cp_commit();
        }
    }

    wmma::fragment<wmma::accumulator, 16, 16, 16, float> cfr[4][2];
#pragma unroll
    for (int i = 0; i < 4; i++)
#pragma unroll
        for (int j = 0; j < 2; j++) wmma::fill_fragment(cfr[i][j], 0.f);

#pragma unroll
    for (int s = 0; s < 2; s++) {
        if (s == 0) cp_wait<1>();
        else cp_wait<0>();
        __syncthreads();
        const __half* As = (const __half*)(smem + s * S_CHUNK);
        const __half* Bs = (const __half*)(smem + s * S_CHUNK + S_TILE);
#pragma unroll
        for (int ks = 0; ks < SK_CH; ks += 16) {
            wmma::fragment<wmma::matrix_a, 16, 16, 16, __half, wmma::row_major> a[4];
            wmma::fragment<wmma::matrix_b, 16, 16, 16, __half, wmma::col_major> b[2];
#pragma unroll
            for (int i = 0; i < 4; i++)
                wmma::load_matrix_sync(a[i], As + (warp_m * 64 + i * 16) * S_LDM + ks, S_LDM);
#pragma unroll
            for (int j = 0; j < 2; j++)
                wmma::load_matrix_sync(b[j], Bs + (warp_n * 32 + j * 16) * S_LDM + ks, S_LDM);
#pragma unroll
            for (int i = 0; i < 4; i++)
#pragma unroll
                for (int j = 0; j < 2; j++)
                    wmma::mma_sync(cfr[i][j], a[i], b[j], cfr[i][j]);
        }
    }

    // Epilogue: frags -> smem -> transform -> fp32 scores to g_S
    __syncthreads();
#pragma unroll
    for (int i = 0; i < 4; i++)
#pragma unroll
        for (int j = 0; j < 2; j++)
            wmma::store_matrix_sync(
                Cs + (warp_m * 64 + i * 16) * C_LDM + warp_n * 32 + j * 16,
                cfr[i][j], C_LDM, wmma::mem_row_major);
    __syncthreads();

    {
        const int r = tid >> 1;             // 0..127
        const int ch = (tid & 1) * 64;      // 0 or 64
        const int i = i0 + r;
        const float nrow = g_norm[i];
        float* orow = g_S + (size_t)i * NN + j0 + ch;
        const float* crow = Cs + r * C_LDM + ch;
        const float4* n4 = (const float4*)(g_norm + j0 + ch);
        const float4* q4 = (const float4*)(qual + j0 + ch);
#pragma unroll
        for (int c4 = 0; c4 < 16; c4++) {
            float4 d = *(const float4*)(crow + c4 * 4);
            float4 nv = n4[c4];
            float4 qv = q4[c4];
            float4 o;
            o.x = qv.x - sqrtf(fmaxf(nrow + nv.x - 2.f * d.x, 0.f));
            o.y = qv.y - sqrtf(fmaxf(nrow + nv.y - 2.f * d.y, 0.f));
            o.z = qv.z - sqrtf(fmaxf(nrow + nv.z - 2.f * d.z, 0.f));
            o.w = qv.w - sqrtf(fmaxf(nrow + nv.w - 2.f * d.w, 0.f));
            *(float4*)(orow + c4 * 4) = o;
        }
    }
}

// ---------------------------------------------------------------------------
// K3: row softmax (exp only). Diagonal forced to qual[row] (true distance 0).
// ---------------------------------------------------------------------------
__global__ void softmax_kernel(const float* __restrict__ qual) {
    const int row = blockIdx.x;
    const int tid = threadIdx.x;
    const float* S = g_S + (size_t)row * NN;
    __half* P = g_Ph + (size_t)row * NN;

    float vals[32];
    float m = -1e30f;
#pragma unroll
    for (int k = 0; k < 32; k++) {
        int j = tid + k * 256;
        float sc = S[j];
        vals[k] = (j == row) ? qual[row] : sc;
        m = fmaxf(m, vals[k]);
    }

    __shared__ float red[8];
#pragma unroll
    for (int off = 16; off; off >>= 1) m = fmaxf(m, __shfl_xor_sync(~0u, m, off));
    if ((tid & 31) == 0) red[tid >> 5] = m;
    __syncthreads();
    if (tid < 8) {
        float x = red[tid];
#pragma unroll
        for (int off = 4; off; off >>= 1) x = fmaxf(x, __shfl_xor_sync(0xffu, x, off));
        if (tid == 0) red[0] = x;
    }
    __syncthreads();
    m = red[0];

    float s = 0.f;
#pragma unroll
    for (int k = 0; k < 32; k++) {
        vals[k] = __expf(vals[k] - m);
        s += vals[k];
    }
    __syncthreads();
#pragma unroll
    for (int off = 16; off; off >>= 1) s += __shfl_xor_sync(~0u, s, off);
    if ((tid & 31) == 0) red[tid >> 5] = s;
    __syncthreads();
    if (tid < 8) {
        float x = red[tid];
#pragma unroll
        for (int off = 4; off; off >>= 1) x += __shfl_xor_sync(0xffu, x, off);
        if (tid == 0) red[0] = x;
    }
    __syncthreads();
    float inv = 1.f / red[0];
#pragma unroll
    for (int k = 0; k < 32; k++) P[tid + k * 256] = __float2half_rn(vals[k] * inv);
}

// ---------------------------------------------------------------------------
// K3b: convert X (f32) -> half
// ---------------------------------------------------------------------------
__global__ void convx_kernel(const float* __restrict__ X) {
    size_t idx = ((size_t)blockIdx.x * blockDim.x + threadIdx.x) * 4;
    float4 v = *(const float4*)(X + idx);
    __half2* dst = (__half2*)(g_Xh + idx);
    dst[0] = __floats2half2_rn(v.x, v.y);
    dst[1] = __floats2half2_rn(v.z, v.w);
}

// ---------------------------------------------------------------------------
// K4: out = P @ X, fp16 wmma. Tile 128x128, BK=64, 3-stage cp.async,
// single-sync multistage mainloop. 128 threads = 4 warps in 2x2,
// warp tile 64x64 (halves LDSM duplication: A 2x, B 2x), 2 CTAs/SM.
// b-fragments loaded inside the j-loop to bound live registers.
// ---------------------------------------------------------------------------
#define BM 128
#define BN 128
#define BK 64
#define NSTG 3
#define A_LDM 72                          // halves (64 data + 8 pad)
#define B_LDM 136                         // halves (128 data + 8 pad)
#define A_STG_BYTES (BM * A_LDM * 2)      // 18432
#define B_STG_BYTES (BK * B_LDM * 2)      // 17408
#define STG_BYTES (A_STG_BYTES + B_STG_BYTES)
#define SMEM_GEMM (NSTG * STG_BYTES)      // 107520
#define NCHUNK (NN / BK)                  // 128

__global__ void __launch_bounds__(128, 2) gemm_kernel(float* __restrict__ out) {
    extern __shared__ __align__(16) char smem[];
    const uint32_t sbase = smem_u32(smem);
    const int tid = threadIdx.x;
    const int warp = tid >> 5;      // 0..3
    const int warp_m = warp >> 1;   // 0..1
    const int warp_n = warp & 1;    // 0..1
    const int m0 = blockIdx.y * BM;
    const int n0 = blockIdx.x * BN;

    // Pointer-carried load state. 128 threads, 16 cp.async16 per thread/chunk.
    const int aRow = tid >> 3, aCol = tid & 7;     // A: rows 0..15 (+16*h), 8 chunks/row
    const int bRow = tid >> 4, bCol = tid & 15;    // B: rows 0..7 (+8*h), 16 chunks/row
    const __half* pA = g_Ph + (size_t)(m0 + aRow) * NN + aCol * 8;
    const __half* pB = g_Xh + (size_t)bRow * GG + n0 + bCol * 8;
    const uint32_t dA0 = sbase + aRow * (A_LDM * 2) + aCol * 16;
    const uint32_t dB0 = sbase + A_STG_BYTES + bRow * (B_LDM * 2) + bCol * 16;

#define ISSUE_CHUNK(stg) do {                                                  \
        const uint32_t _o = (uint32_t)(stg) * STG_BYTES;                       \
        cp_async16(dA0 + _o,                    pA);                           \
        cp_async16(dA0 + _o + 16 * A_LDM * 2,   pA + (size_t)16 * NN);         \
        cp_async16(dA0 + _o + 32 * A_LDM * 2,   pA + (size_t)32 * NN);         \
        cp_async16(dA0 + _o + 48 * A_LDM * 2,   pA + (size_t)48 * NN);         \
        cp_async16(dA0 + _o + 64 * A_LDM * 2,   pA + (size_t)64 * NN);         \
        cp_async16(dA0 + _o + 80 * A_LDM * 2,   pA + (size_t)80 * NN);         \
        cp_async16(dA0 + _o + 96 * A_LDM * 2,   pA + (size_t)96 * NN);         \
        cp_async16(dA0 + _o + 112 * A_LDM * 2,  pA + (size_t)112 * NN);        \
        cp_async16(dB0 + _o,                    pB);                           \
        cp_async16(dB0 + _o + 8 * B_LDM * 2,    pB + (size_t)8 * GG);          \
        cp_async16(dB0 + _o + 16 * B_LDM * 2,   pB + (size_t)16 * GG);         \
        cp_async16(dB0 + _o + 24 * B_LDM * 2,   pB + (size_t)24 * GG);         \
        cp_async16(dB0 + _o + 32 * B_LDM * 2,   pB + (size_t)32 * GG);         \
        cp_async16(dB0 + _o + 40 * B_LDM * 2,   pB + (size_t)40 * GG);         \
        cp_async16(dB0 + _o + 48 * B_LDM * 2,   pB + (size_t)48 * GG);         \
        cp_async16(dB0 + _o + 56 * B_LDM * 2,   pB + (size_t)56 * GG);         \
        cp_commit();                                                           \
        pA += BK;                                                              \
        pB += (size_t)BK * GG;                                                 \
    } while (0)

    wmma::fragment<wmma::accumulator, 16, 16, 16, float> cfr[4][4];
#pragma unroll
    for (int i = 0; i < 4; i++)
#pragma unroll
        for (int j = 0; j < 4; j++) wmma::fill_fragment(cfr[i][j], 0.f);

    ISSUE_CHUNK(0);
    ISSUE_CHUNK(1);

    for (int c = 0; c < NCHUNK; c++) {
        const int st = c % NSTG;
        const __half* Ah = (const __half*)(smem + st * STG_BYTES);
        const __half* Bh = (const __half*)(smem + st * STG_BYTES + A_STG_BYTES);

        if (c + 1 < NCHUNK) cp_wait<NSTG - 2>(); else cp_wait<0>();
        __syncthreads();
        // Refill the stage freed by the previous iteration; overlaps MMAs.
        if (c + NSTG - 1 < NCHUNK) ISSUE_CHUNK((c + NSTG - 1) % NSTG);

#pragma unroll
        for (int ks = 0; ks < BK; ks += 16) {
            wmma::fragment<wmma::matrix_a, 16, 16, 16, __half, wmma::row_major> a[4];
#pragma unroll
            for (int i = 0; i < 4; i++)
                wmma::load_matrix_sync(a[i], Ah + (warp_m * 64 + i * 16) * A_LDM + ks, A_LDM);
#pragma unroll
            for (int j = 0; j < 4; j++) {
                wmma::fragment<wmma::matrix_b, 16, 16, 16, __half, wmma::row_major> b;
                wmma::load_matrix_sync(b, Bh + ks * B_LDM + warp_n * 64 + j * 16, B_LDM);
#pragma unroll
                for (int i = 0; i < 4; i++)
                    wmma::mma_sync(cfr[i][j], a[i], b, cfr[i][j]);
            }
        }
    }
#undef ISSUE_CHUNK

#pragma unroll
    for (int i = 0; i < 4; i++)
#pragma unroll
        for (int j = 0; j < 4; j++)
            wmma::store_matrix_sync(
                out + (size_t)(m0 + warp_m * 64 + i * 16) * GG + n0 + warp_n * 64 + j * 16,
                cfr[i][j], GG, wmma::mem_row_major);
}

// ---------------------------------------------------------------------------
extern "C" void kernel_launch(void* const* d_in, const int* in_sizes, int n_in,
                              void* d_out, int out_size) {
    const float* expr = nullptr;  // N*G
    const float* enc = nullptr;   // N*D
    const float* qual = nullptr;  // N
    for (int i = 0; i < n_in; i++) {
        if (in_sizes[i] == NN * GG) expr = (const float*)d_in[i];
        else if (in_sizes[i] == NN * DD) enc = (const float*)d_in[i];
        else if (in_sizes[i] == NN) qual = (const float*)d_in[i];
    }
    float* out = (float*)d_out;

    cudaFuncSetAttribute(scores_mm_kernel, cudaFuncAttributeMaxDynamicSharedMemorySize,
                         S_SMEM);
    cudaFuncSetAttribute(gemm_kernel, cudaFuncAttributeMaxDynamicSharedMemorySize,
                         SMEM_GEMM);

    norms_kernel<<<NN / 256, 256>>>(enc);
    split_enc_kernel<<<(NN * DD) / 256, 256>>>(enc);
    dim3 g2(NN / 128, NN / 128);
    scores_mm_kernel<<<g2, 256, S_SMEM>>>(qual);
    softmax_kernel<<<NN, 256>>>(qual);
    convx_kernel<<<(NN * GG) / (256 * 4), 256>>>(expr);
    dim3 g4(GG / BN, NN / BM);
    gemm_kernel<<<g4, 128, SMEM_GEMM>>>(out);
}